// round 2
// baseline (speedup 1.0000x reference)
#include <cuda_runtime.h>
#include <math.h>

// Problem constants
#define Bsz 2
#define S   128
#define H   768
#define Dd  384
#define Cc  4
#define I   385            // D+1 (bias_x / bias_y dim)
#define NJR 1540           // J*R = 385*4, W's contiguous inner block per (i,k)
#define MBZ 256            // B*S
#define NBIG (S*NJR)       // 197120, stage-C N dimension per batch

// ---------------- scratch (__device__ globals: allocation-guard legal) ----
__device__ float g_tmp [MBZ*Dd];                    // MLP hidden
__device__ float g_head[MBZ*I];                     // X = [head, 1]
__device__ float g_mid [MBZ*I];                     // Y = [mid, 1]
__device__ float g_tail[MBZ*Dd];                    // Z
__device__ float g_t1 [(size_t)Bsz*I*S*NJR];        // 151,782,400 f = 607 MB
__device__ float g_u  [(size_t)Bsz*S*S*NJR];        //  50,462,720 f = 202 MB
__device__ float g_sc [(size_t)Bsz*S*S*Cc*S];       //  16,777,216 f =  67 MB  [b,x,y,r,z]

// ---------------- MLP: C[m,n] = relu(sum_k A[m,k]*B[n,k] + bias[n]) -------
// M,N multiples of 64, K multiple of 16. C written with row stride ldc.
__global__ void __launch_bounds__(256)
mlp_gemm(const float* __restrict__ A, const float* __restrict__ Bm,
         const float* __restrict__ bias, float* __restrict__ Cm,
         int M, int N, int K, int ldc)
{
    __shared__ float As[16][64];
    __shared__ float Bs[16][64];
    const int m0 = blockIdx.y * 64, n0 = blockIdx.x * 64;
    const int t  = threadIdx.x;
    const int ty = t / 16, tx = t % 16;
    float acc[4][4] = {};
    for (int k0 = 0; k0 < K; k0 += 16) {
        int r = t / 4, c = (t % 4) * 4;
        float4 va = *(const float4*)(A  + (size_t)(m0 + r) * K + k0 + c);
        As[c+0][r] = va.x; As[c+1][r] = va.y; As[c+2][r] = va.z; As[c+3][r] = va.w;
        float4 vb = *(const float4*)(Bm + (size_t)(n0 + r) * K + k0 + c);
        Bs[c+0][r] = vb.x; Bs[c+1][r] = vb.y; Bs[c+2][r] = vb.z; Bs[c+3][r] = vb.w;
        __syncthreads();
        #pragma unroll
        for (int kk = 0; kk < 16; kk++) {
            float a[4], b[4];
            #pragma unroll
            for (int q = 0; q < 4; q++) { a[q] = As[kk][ty*4+q]; b[q] = Bs[kk][tx*4+q]; }
            #pragma unroll
            for (int i2 = 0; i2 < 4; i2++)
                #pragma unroll
                for (int j2 = 0; j2 < 4; j2++) acc[i2][j2] += a[i2] * b[j2];
        }
        __syncthreads();
    }
    #pragma unroll
    for (int i2 = 0; i2 < 4; i2++)
        #pragma unroll
        for (int j2 = 0; j2 < 4; j2++) {
            int m = m0 + ty*4 + i2, n = n0 + tx*4 + j2;
            float v = acc[i2][j2] + bias[n];
            Cm[(size_t)m * ldc + n] = v > 0.f ? v : 0.f;
        }
}

__global__ void set_ones(float* head, float* mid)
{
    int t = threadIdx.x;
    if (t < MBZ) { head[(size_t)t * I + Dd] = 1.f; mid[(size_t)t * I + Dd] = 1.f; }
}

// ---------------- Stage B: t1[b,i,z,(j,r)] = sum_k tail[b,z,k] * W[i,k,(j,r)]
// grid: (13 n-tiles, 2 m-tiles(b), 385 i). 128x128 tile, 8x8 microtile.
__global__ void __launch_bounds__(256)
stageB(const float* __restrict__ W, const float* __restrict__ tail,
       float* __restrict__ t1)
{
    const int n0 = blockIdx.x * 128;
    const int b  = blockIdx.y;            // m0 = b*128; m=(b,z)
    const int i  = blockIdx.z;
    __shared__ float As[16][128];
    __shared__ float Bs[16][128];
    const int t  = threadIdx.x;
    const int ty = t / 16, tx = t % 16;
    float acc[8][8] = {};
    const float* Wi = W + (size_t)i * Dd * NJR;
    for (int k0 = 0; k0 < Dd; k0 += 16) {
        {   // A: tail rows (b*128+m), 16 k — 2 float4 / thread, store transposed
            int m = t >> 1, c0 = (t & 1) * 8;
            const float* ap = tail + (size_t)(b*128 + m) * Dd + k0 + c0;
            float4 v0 = *(const float4*)ap;
            float4 v1 = *(const float4*)(ap + 4);
            As[c0+0][m]=v0.x; As[c0+1][m]=v0.y; As[c0+2][m]=v0.z; As[c0+3][m]=v0.w;
            As[c0+4][m]=v1.x; As[c0+5][m]=v1.y; As[c0+6][m]=v1.z; As[c0+7][m]=v1.w;
        }
        #pragma unroll
        for (int q = 0; q < 2; q++) {     // B: contiguous W rows
            int f = t*2 + q, kk = f >> 5, nq = f & 31;
            int n = n0 + nq*4;
            float4 v = (n < NJR) ? *(const float4*)(Wi + (size_t)(k0+kk)*NJR + n)
                                 : make_float4(0.f,0.f,0.f,0.f);
            *(float4*)&Bs[kk][nq*4] = v;
        }
        __syncthreads();
        #pragma unroll
        for (int kk = 0; kk < 16; kk++) {
            float a[8], bb[8];
            *(float4*)(a)    = *(float4*)&As[kk][ty*8];
            *(float4*)(a+4)  = *(float4*)&As[kk][ty*8+4];
            *(float4*)(bb)   = *(float4*)&Bs[kk][tx*8];
            *(float4*)(bb+4) = *(float4*)&Bs[kk][tx*8+4];
            #pragma unroll
            for (int ii = 0; ii < 8; ii++)
                #pragma unroll
                for (int jj = 0; jj < 8; jj++) acc[ii][jj] += a[ii] * bb[jj];
        }
        __syncthreads();
    }
    const size_t base_bi = ((size_t)b * I + i) * S;
    #pragma unroll
    for (int ii = 0; ii < 8; ii++) {
        int z = ty*8 + ii;
        float* cp = t1 + (base_bi + z) * (size_t)NJR + n0 + tx*8;
        int n = n0 + tx*8;
        if (n < NJR)     *(float4*)cp       = make_float4(acc[ii][0],acc[ii][1],acc[ii][2],acc[ii][3]);
        if (n + 4 < NJR) *(float4*)(cp + 4) = make_float4(acc[ii][4],acc[ii][5],acc[ii][6],acc[ii][7]);
    }
}

// ---------------- Stage C: u[b,x,(z,j,r)] = sum_i X[b,x,i] * t1[b,i,(z,j,r)]
// grid: (NBIG/128 = 1540, b=2)
__global__ void __launch_bounds__(256)
stageC(const float* __restrict__ t1, const float* __restrict__ X,
       float* __restrict__ u)
{
    const int n0 = blockIdx.x * 128;
    const int b  = blockIdx.y;
    __shared__ float As[16][128];
    __shared__ float Bs[16][128];
    const int t  = threadIdx.x;
    const int ty = t / 16, tx = t % 16;
    float acc[8][8] = {};
    const float* Xb = X  + (size_t)b * S * I;
    const float* Tb = t1 + (size_t)b * I * NBIG;
    for (int k0 = 0; k0 < I; k0 += 16) {
        {
            int x = t >> 1, c0 = (t & 1) * 8;
            #pragma unroll
            for (int q = 0; q < 8; q++) {
                int k = k0 + c0 + q;
                As[c0+q][x] = (k < I) ? Xb[(size_t)x * I + k] : 0.f;
            }
        }
        #pragma unroll
        for (int q = 0; q < 2; q++) {
            int f = t*2 + q, kk = f >> 5, nq = f & 31;
            int k = k0 + kk;
            float4 v = (k < I) ? *(const float4*)(Tb + (size_t)k * NBIG + n0 + nq*4)
                               : make_float4(0.f,0.f,0.f,0.f);
            *(float4*)&Bs[kk][nq*4] = v;
        }
        __syncthreads();
        #pragma unroll
        for (int kk = 0; kk < 16; kk++) {
            float a[8], bb[8];
            *(float4*)(a)    = *(float4*)&As[kk][ty*8];
            *(float4*)(a+4)  = *(float4*)&As[kk][ty*8+4];
            *(float4*)(bb)   = *(float4*)&Bs[kk][tx*8];
            *(float4*)(bb+4) = *(float4*)&Bs[kk][tx*8+4];
            #pragma unroll
            for (int ii = 0; ii < 8; ii++)
                #pragma unroll
                for (int jj = 0; jj < 8; jj++) acc[ii][jj] += a[ii] * bb[jj];
        }
        __syncthreads();
    }
    #pragma unroll
    for (int ii = 0; ii < 8; ii++) {
        int xr = ty*8 + ii;
        float* cp = u + ((size_t)(b*S + xr)) * NBIG + n0 + tx*8;
        *(float4*)cp     = make_float4(acc[ii][0],acc[ii][1],acc[ii][2],acc[ii][3]);
        *(float4*)(cp+4) = make_float4(acc[ii][4],acc[ii][5],acc[ii][6],acc[ii][7]);
    }
}

// ---------------- Stage D: score[b,x,y,r,z] = sum_j Y[b,y,j] * u[b,x,z,j,r]
// grid: (zq=4, x=128, b=2); per CTA: y(128) x (32 z * 4 r = 128) over K=385
__global__ void __launch_bounds__(256)
stageD(const float* __restrict__ u, const float* __restrict__ Y,
       float* __restrict__ score)
{
    const int zq = blockIdx.x, x = blockIdx.y, b = blockIdx.z;
    __shared__ float As[16][128];   // [j][y]
    __shared__ float Bs[16][128];   // [j][(zl,r)]
    const int t  = threadIdx.x;
    const int ty = t / 16, tx = t % 16;
    float acc[8][8] = {};
    const float* Yb  = Y + (size_t)b * S * I;
    const float* Ubx = u + ((size_t)(b*S + x)) * NBIG;
    const int z0 = zq * 32;
    for (int k0 = 0; k0 < I; k0 += 16) {
        {
            int y = t >> 1, c0 = (t & 1) * 8;
            #pragma unroll
            for (int q = 0; q < 8; q++) {
                int j = k0 + c0 + q;
                As[c0+q][y] = (j < I) ? Yb[(size_t)y * I + j] : 0.f;
            }
        }
        #pragma unroll
        for (int q = 0; q < 2; q++) {
            int idx = t + q*256;
            int jj = idx >> 5, zl = idx & 31;
            int j = k0 + jj;
            float4 v = (j < I) ? *(const float4*)(Ubx + (size_t)(z0+zl) * NJR + j*4)
                               : make_float4(0.f,0.f,0.f,0.f);
            *(float4*)&Bs[jj][zl*4] = v;
        }
        __syncthreads();
        #pragma unroll
        for (int kk = 0; kk < 16; kk++) {
            float a[8], bb[8];
            *(float4*)(a)    = *(float4*)&As[kk][ty*8];
            *(float4*)(a+4)  = *(float4*)&As[kk][ty*8+4];
            *(float4*)(bb)   = *(float4*)&Bs[kk][tx*8];
            *(float4*)(bb+4) = *(float4*)&Bs[kk][tx*8+4];
            #pragma unroll
            for (int ii = 0; ii < 8; ii++)
                #pragma unroll
                for (int jj = 0; jj < 8; jj++) acc[ii][jj] += a[ii] * bb[jj];
        }
        __syncthreads();
    }
    const size_t outb = ((size_t)(b*S + x)) * S * 512;   // per y: 4*128
    #pragma unroll
    for (int ii = 0; ii < 8; ii++) {
        int y = ty*8 + ii;
        #pragma unroll
        for (int jj = 0; jj < 8; jj++) {
            int n = tx*8 + jj;
            int zl = n >> 2, r = n & 3;
            score[outb + (size_t)y*512 + (size_t)r*128 + (z0 + zl)] = acc[ii][jj];
        }
    }
}

// ---------------- Stage E: masked softmax over z + relu(alpha^T mem) . Vw + Vb
// grid: (yh=2, x=128, b=2), 256 threads, dynamic smem.
#define ALD 129                                  // padded alpha row (bank-safe)
#define SME_FLOATS (256*ALD + 128*64 + 4*64 + 256)
#define SME_BYTES  (SME_FLOATS * 4)

__global__ void __launch_bounds__(256)
stageE(const float* __restrict__ score, const float* __restrict__ mem,
       const float* __restrict__ Vw, const float* __restrict__ Vb,
       float* __restrict__ out)
{
    extern __shared__ float sm[];
    float* alpha = sm;                    // [256][129]  rows m = yl*4+r
    float* mems  = sm + 256*ALD;          // [128][64]
    float* vws   = mems + 128*64;         // [4][64]
    float* outs  = vws + 256;             // [256]
    const int yh = blockIdx.x, x = blockIdx.y, b = blockIdx.z;
    const int t  = threadIdx.x;

    // phase 1: masked softmax over z, one (y,r) row per thread
    {
        int yl = t >> 2, r = t & 3;
        int y  = yh*64 + yl;
        const float* srow = score + ((((size_t)(b*S + x))*S + y)*4 + r) * S;
        float* arow = alpha + (size_t)t * ALD;
        float mx = -1e30f;
        #pragma unroll 4
        for (int zq = 0; zq < 32; zq++) {
            float4 v = *(const float4*)(srow + zq*4);
            float vv[4] = {v.x, v.y, v.z, v.w};
            #pragma unroll
            for (int e = 0; e < 4; e++) {
                int z = zq*4 + e;
                float val = (z >= x && z <= y) ? vv[e] : -1000000.0f;
                arow[z] = val;
                mx = fmaxf(mx, val);
            }
        }
        float ssum = 0.f;
        for (int z = 0; z < 128; z++) { float e = expf(arow[z] - mx); arow[z] = e; ssum += e; }
        float inv = 1.f / ssum;
        for (int z = 0; z < 128; z++) arow[z] *= inv;
        outs[t] = 0.f;
    }
    __syncthreads();

    // phase 2: TS[(y,r),h] = sum_z alpha * mem[z,h]; out += relu(TS)*Vw
    const int tm = t >> 3, tn = t & 7;        // 32 x 8 thread grid, 8x8 microtile
    float outp[8] = {};
    const float* memb = mem + (size_t)b * S * H;
    for (int h0 = 0; h0 < H; h0 += 64) {
        #pragma unroll
        for (int q = 0; q < 8; q++) {
            int f = t + q*256;
            int z = f >> 4, hq = f & 15;
            *(float4*)&mems[z*64 + hq*4] = *(const float4*)(memb + (size_t)z*H + h0 + hq*4);
        }
        { int r = t >> 6, hh = t & 63; vws[r*64 + hh] = Vw[(size_t)r*H + h0 + hh]; }
        __syncthreads();
        float acc[8][8] = {};
        for (int z = 0; z < 128; z++) {
            float a[8], bb[8];
            #pragma unroll
            for (int im = 0; im < 8; im++) a[im] = alpha[(size_t)(tm*8+im)*ALD + z];
            *(float4*)(bb)   = *(float4*)&mems[z*64 + tn*8];
            *(float4*)(bb+4) = *(float4*)&mems[z*64 + tn*8 + 4];
            #pragma unroll
            for (int im = 0; im < 8; im++)
                #pragma unroll
                for (int jn = 0; jn < 8; jn++) acc[im][jn] += a[im] * bb[jn];
        }
        #pragma unroll
        for (int im = 0; im < 8; im++) {
            int m = tm*8 + im, r = m & 3;
            #pragma unroll
            for (int jn = 0; jn < 8; jn++) {
                float v = acc[im][jn];
                v = v > 0.f ? v : 0.f;
                outp[im] += v * vws[r*64 + tn*8 + jn];
            }
        }
        __syncthreads();
    }
    #pragma unroll
    for (int im = 0; im < 8; im++) atomicAdd(&outs[tm*8 + im], outp[im]);
    __syncthreads();
    {
        int m = t, yl = m >> 2, r = m & 3;
        int y = yh*64 + yl;
        out[(((size_t)(b*S + x))*S + y)*4 + r] = outs[m] + Vb[r];
    }
}

// ---------------------------------------------------------------------------
extern "C" void kernel_launch(void* const* d_in, const int* in_sizes, int n_in,
                              void* d_out, int out_size)
{
    const float* memory = (const float*)d_in[0];
    const float* Wh1 = (const float*)d_in[1];  const float* bh1 = (const float*)d_in[2];
    const float* Wh2 = (const float*)d_in[3];  const float* bh2 = (const float*)d_in[4];
    const float* Wt1 = (const float*)d_in[5];  const float* bt1 = (const float*)d_in[6];
    const float* Wt2 = (const float*)d_in[7];  const float* bt2 = (const float*)d_in[8];
    const float* Wm1 = (const float*)d_in[9];  const float* bm1 = (const float*)d_in[10];
    const float* Wm2 = (const float*)d_in[11]; const float* bm2 = (const float*)d_in[12];
    const float* Wtri = (const float*)d_in[13];
    const float* Vw  = (const float*)d_in[14]; const float* Vb  = (const float*)d_in[15];
    float* out = (float*)d_out;

    float *tmp, *head, *mid, *tail, *t1, *u, *score;
    cudaGetSymbolAddress((void**)&tmp,   g_tmp);
    cudaGetSymbolAddress((void**)&head,  g_head);
    cudaGetSymbolAddress((void**)&mid,   g_mid);
    cudaGetSymbolAddress((void**)&tail,  g_tail);
    cudaGetSymbolAddress((void**)&t1,    g_t1);
    cudaGetSymbolAddress((void**)&u,     g_u);
    cudaGetSymbolAddress((void**)&score, g_sc);

    dim3 gm(Dd/64, MBZ/64);
    // head MLP -> X, tail MLP -> Z, mid MLP -> Y (sequential, reuse tmp)
    mlp_gemm<<<gm, 256>>>(memory, Wh1, bh1, tmp,  MBZ, Dd, H,  Dd);
    mlp_gemm<<<gm, 256>>>(tmp,    Wh2, bh2, head, MBZ, Dd, Dd, I);
    mlp_gemm<<<gm, 256>>>(memory, Wt1, bt1, tmp,  MBZ, Dd, H,  Dd);
    mlp_gemm<<<gm, 256>>>(tmp,    Wt2, bt2, tail, MBZ, Dd, Dd, Dd);
    mlp_gemm<<<gm, 256>>>(memory, Wm1, bm1, tmp,  MBZ, Dd, H,  Dd);
    mlp_gemm<<<gm, 256>>>(tmp,    Wm2, bm2, mid,  MBZ, Dd, Dd, I);
    set_ones<<<1, 256>>>(head, mid);

    stageB<<<dim3(13, 2, I),        256>>>(Wtri, tail, t1);
    stageC<<<dim3(NBIG/128, 2),     256>>>(t1, head, u);
    stageD<<<dim3(4, 128, 2),       256>>>(u, mid, score);

    cudaFuncSetAttribute(stageE, cudaFuncAttributeMaxDynamicSharedMemorySize, SME_BYTES);
    stageE<<<dim3(2, 128, 2), 256, SME_BYTES>>>(score, memory, Vw, Vb, out);
}

// round 5
// speedup vs baseline: 1.5105x; 1.5105x over previous
#include <cuda_runtime.h>
#include <cuda_bf16.h>
#include <math.h>
#include <stdint.h>

// Problem constants
#define Bsz 2
#define S   128
#define H   768
#define Dd  384
#define Cc  4
#define I   385            // D+1
#define IA  388            // padded lda for X/Y
#define NJR 1540           // J*R = 385*4
#define MBZ 256            // B*S
#define NBIG (S*NJR)       // 197120

// ---------------- scratch ----------------
__device__ __align__(256) float g_tmp [MBZ*Dd];
__device__ __align__(256) float g_head[MBZ*IA];
__device__ __align__(256) float g_mid [MBZ*IA];
__device__ __align__(256) float g_tail[MBZ*Dd];
__device__ __align__(256) float g_t1 [(size_t)Bsz*I*S*NJR];   // 607 MB
__device__ __align__(256) float g_u  [(size_t)Bsz*S*S*NJR];   // 202 MB
__device__ __align__(256) float g_sc [(size_t)Bsz*S*S*Cc*S];  //  67 MB [b,x,y,r,z]

// ================= helpers =================
__device__ __forceinline__ uint32_t smem_u32(const void* p) {
    uint32_t a;
    asm("{ .reg .u64 t; cvta.to.shared.u64 t, %1; cvt.u32.u64 %0, t; }" : "=r"(a) : "l"(p));
    return a;
}
__device__ __forceinline__ void ldmx4(uint32_t* r, uint32_t addr) {
    asm volatile("ldmatrix.sync.aligned.m8n8.x4.shared.b16 {%0,%1,%2,%3}, [%4];"
        : "=r"(r[0]), "=r"(r[1]), "=r"(r[2]), "=r"(r[3]) : "r"(addr));
}
__device__ __forceinline__ void mma16816(float* d, const uint32_t* a, const uint32_t* b) {
    asm volatile("mma.sync.aligned.m16n8k16.row.col.f32.bf16.bf16.f32 "
        "{%0,%1,%2,%3}, {%4,%5,%6,%7}, {%8,%9}, {%0,%1,%2,%3};"
        : "+f"(d[0]), "+f"(d[1]), "+f"(d[2]), "+f"(d[3])
        : "r"(a[0]), "r"(a[1]), "r"(a[2]), "r"(a[3]), "r"(b[0]), "r"(b[1]));
}

__device__ __forceinline__ void splitpack(const float* f, uint4& hi, uint4& lo) {
    uint32_t h[8], l[8];
    #pragma unroll
    for (int e = 0; e < 8; e++) {
        __nv_bfloat16 bh = __float2bfloat16(f[e]);
        float r = f[e] - __bfloat162float(bh);
        __nv_bfloat16 bl = __float2bfloat16(r);
        h[e] = (uint32_t)__bfloat16_as_ushort(bh);
        l[e] = (uint32_t)__bfloat16_as_ushort(bl);
    }
    hi = make_uint4(h[0]|(h[1]<<16), h[2]|(h[3]<<16), h[4]|(h[5]<<16), h[6]|(h[7]<<16));
    lo = make_uint4(l[0]|(l[1]<<16), l[2]|(l[3]<<16), l[4]|(l[5]<<16), l[6]|(l[7]<<16));
}

// smem layout: padded rows of 72 bf16 (144 B, odd multiple of 16B -> conflict-free ldmatrix)
#define ROWB 144
#define TERM_BYTES (128 * ROWB)        // 18432
#define OFF_AH 0
#define OFF_AL (OFF_AH + TERM_BYTES)
#define OFF_BH (OFF_AL + TERM_BYTES)
#define OFF_BL (OFF_BH + TERM_BYTES)
#define G3_SMEM (OFF_BL + TERM_BYTES)  // 73728 B

// ============ unified split-bf16 HMMA GEMM ============
// D[m,n] = sum_k A[m,k]*B(k,n); M=128 rows, tile N=128, KC=64 chunks, fp32 io.
// dmode=0: B element = Bg[k*ldb + n_global]
// dmode=1: B element = Bg[(n>>2)*ldb + k*4 + (n&3)]; C col n -> (n&3)*128 + (n>>2)
__global__ void __launch_bounds__(256, 2)
gemm3(const float* __restrict__ A, int lda, size_t sA, int aShift,
      const float* __restrict__ Bg, int ldb, size_t sB,
      float* __restrict__ Cg, int ldc, size_t sC, size_t mStrC,
      int K, int Nlimit, int dmode)
{
    extern __shared__ char smem[];
    const int n0 = blockIdx.x * 128;
    const int my = blockIdx.y;
    const int zb = blockIdx.z;
    A  += ((size_t)(zb >> aShift)) * sA + (size_t)my * 128 * lda;
    Bg += (size_t)zb * sB;
    Cg += (size_t)zb * sC + (size_t)my * mStrC;
    const float* Bn = Bg + n0;

    const uint32_t sb = smem_u32(smem);
    const int t = threadIdx.x, wid = t >> 5, lane = t & 31;
    // 8 warps as 4(m) x 2(n): wm4 in 0..3 (32 rows each), wn2 in 0..1 (64 cols each)
    const int wm4 = wid & 3, wn2 = wid >> 2;

    // ldmatrix base addresses
    const uint32_t aBase = sb + OFF_AH
        + (uint32_t)(wm4*32 + (lane & 15)) * ROWB + (uint32_t)((lane >> 4) * 8) * 2;
    const uint32_t bBase = sb + OFF_BH
        + (uint32_t)(wn2*64 + (lane & 7) + (((lane >> 4) & 1) << 3)) * ROWB
        + (uint32_t)(((lane >> 3) & 1) * 8) * 2;

    float acc[2][8][4];
    #pragma unroll
    for (int i = 0; i < 2; i++)
        #pragma unroll
        for (int j = 0; j < 8; j++)
            #pragma unroll
            for (int e = 0; e < 4; e++) acc[i][j][e] = 0.f;

    const int nc = (K + 63) >> 6;
    for (int c = 0; c < nc; c++) {
        const int k0 = c << 6;
        // ---- A tile: 128 rows x 64 k, fp32 -> split bf16 ----
        #pragma unroll
        for (int q = 0; q < 4; q++) {
            int idx = q * 256 + t;            // 1024 = 128 rows x 8 kgroups
            int m = idx >> 3, g = idx & 7;
            int k = k0 + g * 8;
            float f[8];
            if (k + 7 < K) {
                float4 v0 = *(const float4*)(A + (size_t)m * lda + k);
                float4 v1 = *(const float4*)(A + (size_t)m * lda + k + 4);
                f[0]=v0.x; f[1]=v0.y; f[2]=v0.z; f[3]=v0.w;
                f[4]=v1.x; f[5]=v1.y; f[6]=v1.z; f[7]=v1.w;
            } else {
                #pragma unroll
                for (int e = 0; e < 8; e++) f[e] = (k + e < K) ? A[(size_t)m * lda + k + e] : 0.f;
            }
            uint4 hi, lo;
            splitpack(f, hi, lo);
            uint32_t off = (uint32_t)m * ROWB + (uint32_t)g * 16;
            *(uint4*)(smem + OFF_AH + off) = hi;
            *(uint4*)(smem + OFF_AL + off) = lo;
        }
        // ---- B tile: 128 n x 64 k (stored [n][k]) ----
        #pragma unroll
        for (int q = 0; q < 4; q++) {
            int idx = q * 256 + t;
            int n = idx & 127, kg = idx >> 7;
            int Nc = n0 + n;
            bool nok = (Nc < Nlimit);
            float f[8];
            #pragma unroll
            for (int e = 0; e < 8; e++) {
                int ke = k0 + kg * 8 + e;
                float v = 0.f;
                if (nok && ke < K) {
                    v = dmode ? Bg[(size_t)(Nc >> 2) * ldb + (size_t)ke * 4 + (Nc & 3)]
                              : Bn[(size_t)ke * ldb + n];
                }
                f[e] = v;
            }
            uint4 hi, lo;
            splitpack(f, hi, lo);
            uint32_t off = (uint32_t)n * ROWB + (uint32_t)kg * 16;
            *(uint4*)(smem + OFF_BH + off) = hi;
            *(uint4*)(smem + OFF_BL + off) = lo;
        }
        __syncthreads();
        // ---- compute: 4 k16 steps x (2 m-atoms x 8 n-atoms) x 3 terms ----
        #pragma unroll
        for (int ks = 0; ks < 4; ks++) {
            const uint32_t ko = (uint32_t)ks * 32;
            uint32_t Ah[2][4], Al[2][4];
            ldmx4(Ah[0], aBase + ko);
            ldmx4(Ah[1], aBase + 2304 + ko);
            ldmx4(Al[0], aBase + TERM_BYTES + ko);
            ldmx4(Al[1], aBase + TERM_BYTES + 2304 + ko);
            uint32_t Bh[4][4], Bl[4][4];
            #pragma unroll
            for (int nq = 0; nq < 4; nq++) {
                ldmx4(Bh[nq], bBase + (uint32_t)nq * 2304 + ko);
                ldmx4(Bl[nq], bBase + (uint32_t)TERM_BYTES + (uint32_t)nq * 2304 + ko);
            }
            #pragma unroll
            for (int mi = 0; mi < 2; mi++) {
                #pragma unroll
                for (int nq = 0; nq < 4; nq++) {
                    mma16816(acc[mi][2*nq+0], Ah[mi], &Bh[nq][0]);
                    mma16816(acc[mi][2*nq+0], Ah[mi], &Bl[nq][0]);
                    mma16816(acc[mi][2*nq+0], Al[mi], &Bh[nq][0]);
                    mma16816(acc[mi][2*nq+1], Ah[mi], &Bh[nq][2]);
                    mma16816(acc[mi][2*nq+1], Ah[mi], &Bl[nq][2]);
                    mma16816(acc[mi][2*nq+1], Al[mi], &Bh[nq][2]);
                }
            }
        }
        __syncthreads();
    }

    // ---- epilogue: registers -> GMEM ----
    const int row0 = wm4 * 32 + (lane >> 2);
    const int col0 = wn2 * 64 + (lane & 3) * 2;
    #pragma unroll
    for (int mi = 0; mi < 2; mi++) {
        int r0 = row0 + mi * 16;
        #pragma unroll
        for (int na = 0; na < 8; na++) {
            int n = n0 + col0 + na * 8;
            float* d = acc[mi][na];
            if (!dmode) {
                if (n < Nlimit) {
                    *(float2*)(Cg + (size_t)r0 * ldc + n)       = make_float2(d[0], d[1]);
                    *(float2*)(Cg + (size_t)(r0 + 8) * ldc + n) = make_float2(d[2], d[3]);
                }
            } else {
                int c0 = ((n & 3) << 7) + (n >> 2);
                int c1 = (((n + 1) & 3) << 7) + ((n + 1) >> 2);
                Cg[(size_t)r0 * ldc + c0]       = d[0];
                Cg[(size_t)r0 * ldc + c1]       = d[1];
                Cg[(size_t)(r0 + 8) * ldc + c0] = d[2];
                Cg[(size_t)(r0 + 8) * ldc + c1] = d[3];
            }
        }
    }
}

// ---------------- MLP GEMM (SIMT, tiny) ----------------
__global__ void __launch_bounds__(256)
mlp_gemm(const float* __restrict__ A, const float* __restrict__ Bm,
         const float* __restrict__ bias, float* __restrict__ Cm,
         int M, int N, int K, int ldc)
{
    __shared__ float As[16][64];
    __shared__ float Bs[16][64];
    const int m0 = blockIdx.y * 64, n0 = blockIdx.x * 64;
    const int t  = threadIdx.x;
    const int ty = t / 16, tx = t % 16;
    float acc[4][4] = {};
    for (int k0 = 0; k0 < K; k0 += 16) {
        int r = t / 4, c = (t % 4) * 4;
        float4 va = *(const float4*)(A  + (size_t)(m0 + r) * K + k0 + c);
        As[c+0][r] = va.x; As[c+1][r] = va.y; As[c+2][r] = va.z; As[c+3][r] = va.w;
        float4 vb = *(const float4*)(Bm + (size_t)(n0 + r) * K + k0 + c);
        Bs[c+0][r] = vb.x; Bs[c+1][r] = vb.y; Bs[c+2][r] = vb.z; Bs[c+3][r] = vb.w;
        __syncthreads();
        #pragma unroll
        for (int kk = 0; kk < 16; kk++) {
            float a[4], b[4];
            #pragma unroll
            for (int q = 0; q < 4; q++) { a[q] = As[kk][ty*4+q]; b[q] = Bs[kk][tx*4+q]; }
            #pragma unroll
            for (int i2 = 0; i2 < 4; i2++)
                #pragma unroll
                for (int j2 = 0; j2 < 4; j2++) acc[i2][j2] += a[i2] * b[j2];
        }
        __syncthreads();
    }
    #pragma unroll
    for (int i2 = 0; i2 < 4; i2++)
        #pragma unroll
        for (int j2 = 0; j2 < 4; j2++) {
            int m = m0 + ty*4 + i2, n = n0 + tx*4 + j2;
            float v = acc[i2][j2] + bias[n];
            Cm[(size_t)m * ldc + n] = v > 0.f ? v : 0.f;
        }
}

__global__ void set_ones(float* head, float* mid)
{
    int t = threadIdx.x;
    if (t < MBZ) {
        head[(size_t)t * IA + Dd] = 1.f; head[(size_t)t * IA + Dd + 1] = 0.f;
        head[(size_t)t * IA + Dd + 2] = 0.f; head[(size_t)t * IA + Dd + 3] = 0.f;
        mid [(size_t)t * IA + Dd] = 1.f; mid [(size_t)t * IA + Dd + 1] = 0.f;
        mid [(size_t)t * IA + Dd + 2] = 0.f; mid [(size_t)t * IA + Dd + 3] = 0.f;
    }
}

// ---------------- Stage E: masked softmax + relu(alpha^T mem) . Vw + Vb ----
#define ALD 129
#define SME_FLOATS (256*ALD + 128*64 + 4*64 + 256)
#define SME_BYTES  (SME_FLOATS * 4)

__global__ void __launch_bounds__(256)
stageE(const float* __restrict__ score, const float* __restrict__ mem,
       const float* __restrict__ Vw, const float* __restrict__ Vb,
       float* __restrict__ out)
{
    extern __shared__ float sm[];
    float* alpha = sm;
    float* mems  = sm + 256*ALD;
    float* vws   = mems + 128*64;
    float* outs  = vws + 256;
    const int yh = blockIdx.x, x = blockIdx.y, b = blockIdx.z;
    const int t  = threadIdx.x;

    {
        int yl = t >> 2, r = t & 3;
        int y  = yh*64 + yl;
        const float* srow = score + ((((size_t)(b*S + x))*S + y)*4 + r) * S;
        float* arow = alpha + (size_t)t * ALD;
        float mx = -1e30f;
        #pragma unroll 4
        for (int zq = 0; zq < 32; zq++) {
            float4 v = *(const float4*)(srow + zq*4);
            float vv[4] = {v.x, v.y, v.z, v.w};
            #pragma unroll
            for (int e = 0; e < 4; e++) {
                int z = zq*4 + e;
                float val = (z >= x && z <= y) ? vv[e] : -1000000.0f;
                arow[z] = val;
                mx = fmaxf(mx, val);
            }
        }
        float ssum = 0.f;
        for (int z = 0; z < 128; z++) { float e = expf(arow[z] - mx); arow[z] = e; ssum += e; }
        float inv = 1.f / ssum;
        for (int z = 0; z < 128; z++) arow[z] *= inv;
        outs[t] = 0.f;
    }
    __syncthreads();

    const int tm = t >> 3, tn = t & 7;
    float outp[8] = {};
    const float* memb = mem + (size_t)b * S * H;
    for (int h0 = 0; h0 < H; h0 += 64) {
        #pragma unroll
        for (int q = 0; q < 8; q++) {
            int f = t + q*256;
            int z = f >> 4, hq = f & 15;
            *(float4*)&mems[z*64 + hq*4] = *(const float4*)(memb + (size_t)z*H + h0 + hq*4);
        }
        { int r = t >> 6, hh = t & 63; vws[r*64 + hh] = Vw[(size_t)r*H + h0 + hh]; }
        __syncthreads();
        float acc[8][8] = {};
        for (int z = 0; z < 128; z++) {
            float a[8], bb[8];
            #pragma unroll
            for (int im = 0; im < 8; im++) a[im] = alpha[(size_t)(tm*8+im)*ALD + z];
            *(float4*)(bb)   = *(float4*)&mems[z*64 + tn*8];
            *(float4*)(bb+4) = *(float4*)&mems[z*64 + tn*8 + 4];
            #pragma unroll
            for (int im = 0; im < 8; im++)
                #pragma unroll
                for (int jn = 0; jn < 8; jn++) acc[im][jn] += a[im] * bb[jn];
        }
        #pragma unroll
        for (int im = 0; im < 8; im++) {
            int m = tm*8 + im, r = m & 3;
            #pragma unroll
            for (int jn = 0; jn < 8; jn++) {
                float v = acc[im][jn];
                v = v > 0.f ? v : 0.f;
                outp[im] += v * vws[r*64 + tn*8 + jn];
            }
        }
        __syncthreads();
    }
    #pragma unroll
    for (int im = 0; im < 8; im++) atomicAdd(&outs[tm*8 + im], outp[im]);
    __syncthreads();
    {
        int m = t, yl = m >> 2, r = m & 3;
        int y = yh*64 + yl;
        out[(((size_t)(b*S + x))*S + y)*4 + r] = outs[m] + Vb[r];
    }
}

// ---------------------------------------------------------------------------
extern "C" void kernel_launch(void* const* d_in, const int* in_sizes, int n_in,
                              void* d_out, int out_size)
{
    const float* memory = (const float*)d_in[0];
    const float* Wh1 = (const float*)d_in[1];  const float* bh1 = (const float*)d_in[2];
    const float* Wh2 = (const float*)d_in[3];  const float* bh2 = (const float*)d_in[4];
    const float* Wt1 = (const float*)d_in[5];  const float* bt1 = (const float*)d_in[6];
    const float* Wt2 = (const float*)d_in[7];  const float* bt2 = (const float*)d_in[8];
    const float* Wm1 = (const float*)d_in[9];  const float* bm1 = (const float*)d_in[10];
    const float* Wm2 = (const float*)d_in[11]; const float* bm2 = (const float*)d_in[12];
    const float* Wtri = (const float*)d_in[13];
    const float* Vw  = (const float*)d_in[14]; const float* Vb  = (const float*)d_in[15];
    float* out = (float*)d_out;

    float *tmp, *head, *mid, *tail, *t1, *u, *score;
    cudaGetSymbolAddress((void**)&tmp,   g_tmp);
    cudaGetSymbolAddress((void**)&head,  g_head);
    cudaGetSymbolAddress((void**)&mid,   g_mid);
    cudaGetSymbolAddress((void**)&tail,  g_tail);
    cudaGetSymbolAddress((void**)&t1,    g_t1);
    cudaGetSymbolAddress((void**)&u,     g_u);
    cudaGetSymbolAddress((void**)&score, g_sc);

    dim3 gm(Dd/64, MBZ/64);
    mlp_gemm<<<gm, 256>>>(memory, Wh1, bh1, tmp,  MBZ, Dd, H,  Dd);
    mlp_gemm<<<gm, 256>>>(tmp,    Wh2, bh2, head, MBZ, Dd, Dd, IA);
    mlp_gemm<<<gm, 256>>>(memory, Wt1, bt1, tmp,  MBZ, Dd, H,  Dd);
    mlp_gemm<<<gm, 256>>>(tmp,    Wt2, bt2, tail, MBZ, Dd, Dd, Dd);
    mlp_gemm<<<gm, 256>>>(memory, Wm1, bm1, tmp,  MBZ, Dd, H,  Dd);
    mlp_gemm<<<gm, 256>>>(tmp,    Wm2, bm2, mid,  MBZ, Dd, Dd, IA);
    set_ones<<<1, 256>>>(head, mid);

    cudaFuncSetAttribute(gemm3, cudaFuncAttributeMaxDynamicSharedMemorySize, G3_SMEM);

    // Stage B: t1[b,i,z,(jr)] = sum_k tail[b*128+z,k] * W[i,k,(jr)]
    gemm3<<<dim3(13, 2, I), 256, G3_SMEM>>>(
        tail, Dd, 0, 0,
        Wtri, NJR, (size_t)Dd * NJR,
        t1, NJR, (size_t)128 * NJR, (size_t)I * 128 * NJR,
        Dd, NJR, 0);

    // Stage C: u[b,x,(zjr)] = sum_i head[b*128+x,i] * t1[b,i,(zjr)]
    gemm3<<<dim3(NBIG/128, 1, 2), 256, G3_SMEM>>>(
        head, IA, (size_t)128 * IA, 0,
        t1, NBIG, (size_t)I * NBIG,
        u, NBIG, (size_t)128 * NBIG, 0,
        I, NBIG, 0);

    // Stage D: score[b,x,y,r,z] = sum_j mid[b*128+y,j] * u[b,x,z,j,r]
    gemm3<<<dim3(4, 1, 256), 256, G3_SMEM>>>(
        mid, IA, (size_t)128 * IA, 7,
        u, NJR, (size_t)NBIG,
        score, 512, (size_t)65536, 0,
        I, 512, 1);

    cudaFuncSetAttribute(stageE, cudaFuncAttributeMaxDynamicSharedMemorySize, SME_BYTES);
    stageE<<<dim3(2, 128, 2), 256, SME_BYTES>>>(score, memory, Vw, Vb, out);
}

// round 6
// speedup vs baseline: 1.9082x; 1.2633x over previous
#include <cuda_runtime.h>
#include <cuda_bf16.h>
#include <math.h>
#include <stdint.h>

// Problem constants
#define Bsz 2
#define S   128
#define H   768
#define Dd  384
#define Cc  4
#define I   385            // D+1
#define IA  388            // padded lda for X/Y
#define NJR 1540           // J*R = 385*4
#define MBZ 256            // B*S
#define NBIG (S*NJR)       // 197120

// ---------------- scratch ----------------
__device__ __align__(256) float g_tmp [3*MBZ*Dd];
__device__ __align__(256) float g_head[MBZ*IA];
__device__ __align__(256) float g_mid [MBZ*IA];
__device__ __align__(256) float g_tail[MBZ*Dd];
__device__ __align__(256) float g_t1 [(size_t)Bsz*I*S*NJR];   // 607 MB
__device__ __align__(256) float g_u  [(size_t)Bsz*S*S*NJR];   // 202 MB
__device__ __align__(256) float g_sc [(size_t)Bsz*S*S*Cc*S];  //  67 MB [b,x,y,r,z]

// ================= helpers =================
__device__ __forceinline__ uint32_t smem_u32(const void* p) {
    uint32_t a;
    asm("{ .reg .u64 t; cvta.to.shared.u64 t, %1; cvt.u32.u64 %0, t; }" : "=r"(a) : "l"(p));
    return a;
}
__device__ __forceinline__ void ldmx4(uint32_t* r, uint32_t addr) {
    asm volatile("ldmatrix.sync.aligned.m8n8.x4.shared.b16 {%0,%1,%2,%3}, [%4];"
        : "=r"(r[0]), "=r"(r[1]), "=r"(r[2]), "=r"(r[3]) : "r"(addr));
}
__device__ __forceinline__ void mma16816(float* d, const uint32_t* a, const uint32_t* b) {
    asm volatile("mma.sync.aligned.m16n8k16.row.col.f32.bf16.bf16.f32 "
        "{%0,%1,%2,%3}, {%4,%5,%6,%7}, {%8,%9}, {%0,%1,%2,%3};"
        : "+f"(d[0]), "+f"(d[1]), "+f"(d[2]), "+f"(d[3])
        : "r"(a[0]), "r"(a[1]), "r"(a[2]), "r"(a[3]), "r"(b[0]), "r"(b[1]));
}
__device__ __forceinline__ void cpasync16(uint32_t dst, const void* src, int srcbytes) {
    asm volatile("cp.async.cg.shared.global [%0], [%1], 16, %2;"
        :: "r"(dst), "l"(src), "r"(srcbytes) : "memory");
}
#define CP_COMMIT() asm volatile("cp.async.commit_group;" ::: "memory")
#define CP_WAIT1()  asm volatile("cp.async.wait_group 1;" ::: "memory")
#define CP_WAIT0()  asm volatile("cp.async.wait_group 0;" ::: "memory")

__device__ __forceinline__ void splitpack(const float* f, uint4& hi, uint4& lo) {
    uint32_t h[8], l[8];
    #pragma unroll
    for (int e = 0; e < 8; e++) {
        __nv_bfloat16 bh = __float2bfloat16(f[e]);
        float r = f[e] - __bfloat162float(bh);
        __nv_bfloat16 bl = __float2bfloat16(r);
        h[e] = (uint32_t)__bfloat16_as_ushort(bh);
        l[e] = (uint32_t)__bfloat16_as_ushort(bl);
    }
    hi = make_uint4(h[0]|(h[1]<<16), h[2]|(h[3]<<16), h[4]|(h[5]<<16), h[6]|(h[7]<<16));
    lo = make_uint4(l[0]|(l[1]<<16), l[2]|(l[3]<<16), l[4]|(l[5]<<16), l[6]|(l[7]<<16));
}

// bf16 planes: rows of 40 bf16 = 80 B (odd multiple of 16B -> conflict-free ldmatrix)
#define KC    32
#define ROWB  80
#define PLANE (128 * ROWB)             // 10240
#define OFF_AH 0
#define OFF_AL (OFF_AH + PLANE)
#define OFF_BH (OFF_AL + PLANE)
#define OFF_BL (OFF_BH + PLANE)
#define STG_A  (OFF_BL + PLANE)        // 40960; 2 x 16384 fp32 staging for A
#define STG_B  (STG_A + 32768)         // 73728; 2 x 16384 fp32 staging for B
#define G3_SMEM (STG_B + 32768)        // 106496 B

// ============ unified split-bf16 HMMA GEMM, cp.async pipelined ============
// D[m,n] = sum_k A[m,k]*B(k,n); M=128 rows, tile N=128, KC=32 chunks, fp32 io.
// dmode=0: B element = Bg[k*ldb + n_global]
// dmode=1: B element = Bg[(n>>2)*ldb + k*4 + (n&3)]; C col n -> (n&3)*128 + (n>>2)
__global__ void __launch_bounds__(256, 2)
gemm3(const float* __restrict__ A, int lda, size_t sA, int aShift,
      const float* __restrict__ Bg, int ldb, size_t sB,
      float* __restrict__ Cg, int ldc, size_t sC, size_t mStrC,
      int K, int Nlimit, int dmode)
{
    extern __shared__ char smem[];
    const int n0 = blockIdx.x * 128;
    const int my = blockIdx.y;
    const int zb = blockIdx.z;
    A  += ((size_t)(zb >> aShift)) * sA + (size_t)my * 128 * lda;
    Bg += (size_t)zb * sB;
    Cg += (size_t)zb * sC + (size_t)my * mStrC;

    const uint32_t sb = smem_u32(smem);
    const int t = threadIdx.x, wid = t >> 5, lane = t & 31;
    const int wm4 = wid & 3, wn2 = wid >> 2;   // 4(m) x 2(n) warps

    const uint32_t aBase = sb + OFF_AH
        + (uint32_t)(wm4*32 + (lane & 15)) * ROWB + (uint32_t)((lane >> 4) * 16);
    const uint32_t bBase = sb + OFF_BH
        + (uint32_t)(wn2*64 + (lane & 7) + (((lane >> 4) & 1) << 3)) * ROWB
        + (uint32_t)(((lane >> 3) & 1) * 16);

    float acc[2][8][4];
    #pragma unroll
    for (int i = 0; i < 2; i++)
        #pragma unroll
        for (int j = 0; j < 8; j++)
            #pragma unroll
            for (int e = 0; e < 4; e++) acc[i][j][e] = 0.f;

    const int nc = (K + KC - 1) / KC;

    // ---- async issue of one chunk's raw fp32 tiles into staging ----
    auto issue = [&](int c) {
        const int buf = c & 1;
        const int k0 = c * KC;
        const uint32_t dstA = sb + STG_A + (uint32_t)buf * 16384u;
        #pragma unroll
        for (int q = 0; q < 2; q++) {
            int idx = q * 256 + t;          // 512 items: m(128) x kg(4, 8 floats)
            int m = idx >> 2, kg = idx & 3;
            int k = k0 + kg * 8;
            const float* src = A + (size_t)m * lda + k;
            int b0 = K - k;     b0 = b0 < 0 ? 0 : (b0 > 4 ? 4 : b0); b0 *= 4;
            int b1 = K - k - 4; b1 = b1 < 0 ? 0 : (b1 > 4 ? 4 : b1); b1 *= 4;
            cpasync16(dstA + (uint32_t)idx * 32u,       b0 ? src     : A, b0);
            cpasync16(dstA + (uint32_t)idx * 32u + 16u, b1 ? src + 4 : A, b1);
        }
        const uint32_t dstB = sb + STG_B + (uint32_t)buf * 16384u;
        #pragma unroll
        for (int q = 0; q < 4; q++) {
            int idx = q * 256 + t;          // 1024 items: ke(32) x n4(32 groups of 4)
            int kel = idx >> 5, n4 = (idx & 31) * 4;
            int ke = k0 + kel;
            int Nc = n0 + n4;
            int bb = (ke < K && Nc < Nlimit) ? 16 : 0;
            const float* src;
            if (dmode) src = Bg + (size_t)(Nc >> 2) * ldb + (size_t)ke * 4;
            else       src = Bg + (size_t)ke * ldb + Nc;
            cpasync16(dstB + (uint32_t)(kel * 128 + n4) * 4u, bb ? src : Bg, bb);
        }
        CP_COMMIT();
    };

    issue(0);

    for (int c = 0; c < nc; c++) {
        const int buf = c & 1;
        if (c + 1 < nc) { issue(c + 1); CP_WAIT1(); }
        else            { CP_WAIT0(); }
        __syncthreads();     // staging(c) visible to all; MMA(c-1) done with planes

        // ---- convert A: staging -> split bf16 planes ----
        #pragma unroll
        for (int q = 0; q < 2; q++) {
            int idx = q * 256 + t;
            int m = idx >> 2, kg = idx & 3;
            const float4* sp = (const float4*)(smem + STG_A + buf * 16384 + idx * 32);
            float4 v0 = sp[0], v1 = sp[1];
            float f[8] = {v0.x, v0.y, v0.z, v0.w, v1.x, v1.y, v1.z, v1.w};
            uint4 hi, lo;
            splitpack(f, hi, lo);
            *(uint4*)(smem + OFF_AH + m * ROWB + kg * 16) = hi;
            *(uint4*)(smem + OFF_AL + m * ROWB + kg * 16) = lo;
        }
        // ---- convert B: staging [ke][n] -> split bf16 planes [n][k] ----
        {
            const float* sp = (const float*)(smem + STG_B + buf * 16384);
            #pragma unroll
            for (int q = 0; q < 2; q++) {
                int idx = q * 256 + t;
                int n = idx & 127, kg = idx >> 7;
                float f[8];
                #pragma unroll
                for (int e = 0; e < 8; e++) f[e] = sp[(kg * 8 + e) * 128 + n];
                uint4 hi, lo;
                splitpack(f, hi, lo);
                *(uint4*)(smem + OFF_BH + n * ROWB + kg * 16) = hi;
                *(uint4*)(smem + OFF_BL + n * ROWB + kg * 16) = lo;
            }
        }
        __syncthreads();

        // ---- MMA: 2 k16 steps x (2 m-atoms x 4 n-quads) x 3 terms ----
        #pragma unroll
        for (int ks = 0; ks < 2; ks++) {
            const uint32_t ko = (uint32_t)ks * 32;
            uint32_t Ah[2][4], Al[2][4];
            ldmx4(Ah[0], aBase + ko);
            ldmx4(Ah[1], aBase + 1280 + ko);
            ldmx4(Al[0], aBase + PLANE + ko);
            ldmx4(Al[1], aBase + PLANE + 1280 + ko);
            uint32_t Bh[4][4], Bl[4][4];
            #pragma unroll
            for (int nq = 0; nq < 4; nq++) {
                ldmx4(Bh[nq], bBase + (uint32_t)nq * 1280 + ko);
                ldmx4(Bl[nq], bBase + (uint32_t)PLANE + (uint32_t)nq * 1280 + ko);
            }
            #pragma unroll
            for (int mi = 0; mi < 2; mi++) {
                #pragma unroll
                for (int nq = 0; nq < 4; nq++) {
                    mma16816(acc[mi][2*nq+0], Ah[mi], &Bh[nq][0]);
                    mma16816(acc[mi][2*nq+0], Ah[mi], &Bl[nq][0]);
                    mma16816(acc[mi][2*nq+0], Al[mi], &Bh[nq][0]);
                    mma16816(acc[mi][2*nq+1], Ah[mi], &Bh[nq][2]);
                    mma16816(acc[mi][2*nq+1], Ah[mi], &Bl[nq][2]);
                    mma16816(acc[mi][2*nq+1], Al[mi], &Bh[nq][2]);
                }
            }
        }
    }

    // ---- epilogue: registers -> GMEM ----
    const int row0 = wm4 * 32 + (lane >> 2);
    const int col0 = wn2 * 64 + (lane & 3) * 2;
    #pragma unroll
    for (int mi = 0; mi < 2; mi++) {
        int r0 = row0 + mi * 16;
        #pragma unroll
        for (int na = 0; na < 8; na++) {
            int n = n0 + col0 + na * 8;
            float* d = acc[mi][na];
            if (!dmode) {
                if (n < Nlimit) {
                    *(float2*)(Cg + (size_t)r0 * ldc + n)       = make_float2(d[0], d[1]);
                    *(float2*)(Cg + (size_t)(r0 + 8) * ldc + n) = make_float2(d[2], d[3]);
                }
            } else {
                int c0 = ((n & 3) << 7) + (n >> 2);
                int c1 = (((n + 1) & 3) << 7) + ((n + 1) >> 2);
                Cg[(size_t)r0 * ldc + c0]       = d[0];
                Cg[(size_t)r0 * ldc + c1]       = d[1];
                Cg[(size_t)(r0 + 8) * ldc + c0] = d[2];
                Cg[(size_t)(r0 + 8) * ldc + c1] = d[3];
            }
        }
    }
}

// ---------------- MLP GEMMs (SIMT, tiny) ----------------
__device__ __forceinline__ void mlp_body(
    const float* __restrict__ A, const float* __restrict__ Bm,
    const float* __restrict__ bias, float* __restrict__ Cm, int K, int ldc)
{
    __shared__ float As[16][64];
    __shared__ float Bs[16][64];
    const int m0 = blockIdx.y * 64, n0 = blockIdx.x * 64;
    const int t  = threadIdx.x;
    const int ty = t / 16, tx = t % 16;
    float acc[4][4] = {};
    for (int k0 = 0; k0 < K; k0 += 16) {
        int r = t / 4, c = (t % 4) * 4;
        float4 va = *(const float4*)(A  + (size_t)(m0 + r) * K + k0 + c);
        As[c+0][r] = va.x; As[c+1][r] = va.y; As[c+2][r] = va.z; As[c+3][r] = va.w;
        float4 vb = *(const float4*)(Bm + (size_t)(n0 + r) * K + k0 + c);
        Bs[c+0][r] = vb.x; Bs[c+1][r] = vb.y; Bs[c+2][r] = vb.z; Bs[c+3][r] = vb.w;
        __syncthreads();
        #pragma unroll
        for (int kk = 0; kk < 16; kk++) {
            float a[4], b[4];
            #pragma unroll
            for (int q = 0; q < 4; q++) { a[q] = As[kk][ty*4+q]; b[q] = Bs[kk][tx*4+q]; }
            #pragma unroll
            for (int i2 = 0; i2 < 4; i2++)
                #pragma unroll
                for (int j2 = 0; j2 < 4; j2++) acc[i2][j2] += a[i2] * b[j2];
        }
        __syncthreads();
    }
    #pragma unroll
    for (int i2 = 0; i2 < 4; i2++)
        #pragma unroll
        for (int j2 = 0; j2 < 4; j2++) {
            int m = m0 + ty*4 + i2, n = n0 + tx*4 + j2;
            float v = acc[i2][j2] + bias[n];
            Cm[(size_t)m * ldc + n] = v > 0.f ? v : 0.f;
        }
}

__global__ void __launch_bounds__(256)
mlp_l1(const float* __restrict__ Ain,
       const float* __restrict__ W0, const float* __restrict__ b0,
       const float* __restrict__ W1, const float* __restrict__ b1,
       const float* __restrict__ W2, const float* __restrict__ b2,
       float* __restrict__ Cout)
{
    const float* W = (blockIdx.z == 0) ? W0 : (blockIdx.z == 1) ? W1 : W2;
    const float* b = (blockIdx.z == 0) ? b0 : (blockIdx.z == 1) ? b1 : b2;
    mlp_body(Ain, W, b, Cout + (size_t)blockIdx.z * MBZ * Dd, H, Dd);
}

__global__ void __launch_bounds__(256)
mlp_l2(const float* __restrict__ A, const float* __restrict__ Bm,
       const float* __restrict__ bias, float* __restrict__ Cm, int ldc)
{
    mlp_body(A, Bm, bias, Cm, Dd, ldc);
}

__global__ void set_ones(float* head, float* mid)
{
    int t = threadIdx.x;
    if (t < MBZ) {
        head[(size_t)t * IA + Dd] = 1.f; head[(size_t)t * IA + Dd + 1] = 0.f;
        head[(size_t)t * IA + Dd + 2] = 0.f; head[(size_t)t * IA + Dd + 3] = 0.f;
        mid [(size_t)t * IA + Dd] = 1.f; mid [(size_t)t * IA + Dd + 1] = 0.f;
        mid [(size_t)t * IA + Dd + 2] = 0.f; mid [(size_t)t * IA + Dd + 3] = 0.f;
    }
}

// ---------------- Stage E: masked softmax + relu(alpha^T mem) . Vw + Vb ----
#define ALD 129
#define SME_FLOATS (256*ALD + 128*64 + 4*64 + 256)
#define SME_BYTES  (SME_FLOATS * 4)

__global__ void __launch_bounds__(256)
stageE(const float* __restrict__ score, const float* __restrict__ mem,
       const float* __restrict__ Vw, const float* __restrict__ Vb,
       float* __restrict__ out)
{
    extern __shared__ float sm[];
    float* alpha = sm;
    float* mems  = sm + 256*ALD;
    float* vws   = mems + 128*64;
    float* outs  = vws + 256;
    const int yh = blockIdx.x, x = blockIdx.y, b = blockIdx.z;
    const int t  = threadIdx.x;

    {
        int yl = t >> 2, r = t & 3;
        int y  = yh*64 + yl;
        const float* srow = score + ((((size_t)(b*S + x))*S + y)*4 + r) * S;
        float* arow = alpha + (size_t)t * ALD;
        float mx = -1e30f;
        #pragma unroll 4
        for (int zq = 0; zq < 32; zq++) {
            float4 v = *(const float4*)(srow + zq*4);
            float vv[4] = {v.x, v.y, v.z, v.w};
            #pragma unroll
            for (int e = 0; e < 4; e++) {
                int z = zq*4 + e;
                float val = (z >= x && z <= y) ? vv[e] : -1000000.0f;
                arow[z] = val;
                mx = fmaxf(mx, val);
            }
        }
        float ssum = 0.f;
        for (int z = 0; z < 128; z++) { float e = expf(arow[z] - mx); arow[z] = e; ssum += e; }
        float inv = 1.f / ssum;
        for (int z = 0; z < 128; z++) arow[z] *= inv;
        outs[t] = 0.f;
    }
    __syncthreads();

    const int tm = t >> 3, tn = t & 7;
    float outp[8] = {};
    const float* memb = mem + (size_t)b * S * H;
    for (int h0 = 0; h0 < H; h0 += 64) {
        #pragma unroll
        for (int q = 0; q < 8; q++) {
            int f = t + q*256;
            int z = f >> 4, hq = f & 15;
            *(float4*)&mems[z*64 + hq*4] = *(const float4*)(memb + (size_t)z*H + h0 + hq*4);
        }
        { int r = t >> 6, hh = t & 63; vws[r*64 + hh] = Vw[(size_t)r*H + h0 + hh]; }
        __syncthreads();
        float acc[8][8] = {};
        for (int z = 0; z < 128; z++) {
            float a[8], bb[8];
            #pragma unroll
            for (int im = 0; im < 8; im++) a[im] = alpha[(size_t)(tm*8+im)*ALD + z];
            *(float4*)(bb)   = *(float4*)&mems[z*64 + tn*8];
            *(float4*)(bb+4) = *(float4*)&mems[z*64 + tn*8 + 4];
            #pragma unroll
            for (int im = 0; im < 8; im++)
                #pragma unroll
                for (int jn = 0; jn < 8; jn++) acc[im][jn] += a[im] * bb[jn];
        }
        #pragma unroll
        for (int im = 0; im < 8; im++) {
            int m = tm*8 + im, r = m & 3;
            #pragma unroll
            for (int jn = 0; jn < 8; jn++) {
                float v = acc[im][jn];
                v = v > 0.f ? v : 0.f;
                outp[im] += v * vws[r*64 + tn*8 + jn];
            }
        }
        __syncthreads();
    }
    #pragma unroll
    for (int im = 0; im < 8; im++) atomicAdd(&outs[tm*8 + im], outp[im]);
    __syncthreads();
    {
        int m = t, yl = m >> 2, r = m & 3;
        int y = yh*64 + yl;
        out[(((size_t)(b*S + x))*S + y)*4 + r] = outs[m] + Vb[r];
    }
}

// ---------------------------------------------------------------------------
extern "C" void kernel_launch(void* const* d_in, const int* in_sizes, int n_in,
                              void* d_out, int out_size)
{
    const float* memory = (const float*)d_in[0];
    const float* Wh1 = (const float*)d_in[1];  const float* bh1 = (const float*)d_in[2];
    const float* Wh2 = (const float*)d_in[3];  const float* bh2 = (const float*)d_in[4];
    const float* Wt1 = (const float*)d_in[5];  const float* bt1 = (const float*)d_in[6];
    const float* Wt2 = (const float*)d_in[7];  const float* bt2 = (const float*)d_in[8];
    const float* Wm1 = (const float*)d_in[9];  const float* bm1 = (const float*)d_in[10];
    const float* Wm2 = (const float*)d_in[11]; const float* bm2 = (const float*)d_in[12];
    const float* Wtri = (const float*)d_in[13];
    const float* Vw  = (const float*)d_in[14]; const float* Vb  = (const float*)d_in[15];
    float* out = (float*)d_out;

    float *tmp, *head, *mid, *tail, *t1, *u, *score;
    cudaGetSymbolAddress((void**)&tmp,   g_tmp);
    cudaGetSymbolAddress((void**)&head,  g_head);
    cudaGetSymbolAddress((void**)&mid,   g_mid);
    cudaGetSymbolAddress((void**)&tail,  g_tail);
    cudaGetSymbolAddress((void**)&t1,    g_t1);
    cudaGetSymbolAddress((void**)&u,     g_u);
    cudaGetSymbolAddress((void**)&score, g_sc);

    dim3 gm(Dd/64, MBZ/64);
    // launches 1-5 (cheap), so launch #6 = stageB gets profiled by ncu -s 5 -c 1
    set_ones<<<1, 256>>>(head, mid);                                       // 1
    mlp_l1<<<dim3(Dd/64, MBZ/64, 3), 256>>>(memory, Wh1, bh1, Wt1, bt1,
                                            Wm1, bm1, tmp);                // 2
    mlp_l2<<<gm, 256>>>(tmp,             Wh2, bh2, head, IA);              // 3
    mlp_l2<<<gm, 256>>>(tmp + MBZ*Dd,    Wt2, bt2, tail, Dd);              // 4
    mlp_l2<<<gm, 256>>>(tmp + 2*MBZ*Dd,  Wm2, bm2, mid,  IA);              // 5

    cudaFuncSetAttribute(gemm3, cudaFuncAttributeMaxDynamicSharedMemorySize, G3_SMEM);

    // Stage B (launch 6): t1[b,i,z,(jr)] = sum_k tail[b*128+z,k] * W[i,k,(jr)]
    gemm3<<<dim3(13, 2, I), 256, G3_SMEM>>>(
        tail, Dd, 0, 0,
        Wtri, NJR, (size_t)Dd * NJR,
        t1, NJR, (size_t)128 * NJR, (size_t)I * 128 * NJR,
        Dd, NJR, 0);

    // Stage C: u[b,x,(zjr)] = sum_i head[b*128+x,i] * t1[b,i,(zjr)]
    gemm3<<<dim3(NBIG/128, 1, 2), 256, G3_SMEM>>>(
        head, IA, (size_t)128 * IA, 0,
        t1, NBIG, (size_t)I * NBIG,
        u, NBIG, (size_t)128 * NBIG, 0,
        I, NBIG, 0);

    // Stage D: score[b,x,y,r,z] = sum_j mid[b*128+y,j] * u[b,x,z,j,r]
    gemm3<<<dim3(4, 1, 256), 256, G3_SMEM>>>(
        mid, IA, (size_t)128 * IA, 7,
        u, NJR, (size_t)NBIG,
        score, 512, (size_t)65536, 0,
        I, 512, 1);

    cudaFuncSetAttribute(stageE, cudaFuncAttributeMaxDynamicSharedMemorySize, SME_BYTES);
    stageE<<<dim3(2, 128, 2), 256, SME_BYTES>>>(score, memory, Vw, Vb, out);
}

// round 10
// speedup vs baseline: 2.4558x; 1.2870x over previous
#include <cuda_runtime.h>
#include <cuda_bf16.h>
#include <math.h>
#include <stdint.h>

// Problem constants
#define Bsz 2
#define S   128
#define H   768
#define Dd  384
#define Cc  4
#define I   385            // D+1
#define IA  388            // padded lda for X/Y
#define NJR 1540           // J*R = 385*4
#define MBZ 256            // B*S
#define NBIG (S*NJR)       // 197120

// ---------------- scratch ----------------
__device__ __align__(256) float g_tmp [3*MBZ*Dd];
__device__ __align__(256) float g_head[MBZ*IA];
__device__ __align__(256) float g_mid [MBZ*IA];
__device__ __align__(256) float g_tail[MBZ*Dd];
__device__ __align__(256) float g_t1 [(size_t)Bsz*I*S*NJR];   // 607 MB
__device__ __align__(256) float g_u  [(size_t)Bsz*S*S*NJR];   // 202 MB
__device__ __align__(256) float g_sc [(size_t)Bsz*S*S*Cc*S];  //  67 MB [b,x,y,r,z]
__device__ __align__(256) __nv_bfloat16 g_memh[Bsz*H*S];      // mem^T hi  [b][h][z]
__device__ __align__(256) __nv_bfloat16 g_meml[Bsz*H*S];      // mem^T lo

// ================= helpers =================
__device__ __forceinline__ uint32_t smem_u32(const void* p) {
    uint32_t a;
    asm("{ .reg .u64 t; cvta.to.shared.u64 t, %1; cvt.u32.u64 %0, t; }" : "=r"(a) : "l"(p));
    return a;
}
__device__ __forceinline__ void ldmx4(uint32_t* r, uint32_t addr) {
    asm volatile("ldmatrix.sync.aligned.m8n8.x4.shared.b16 {%0,%1,%2,%3}, [%4];"
        : "=r"(r[0]), "=r"(r[1]), "=r"(r[2]), "=r"(r[3]) : "r"(addr));
}
__device__ __forceinline__ void mma16816(float* d, const uint32_t* a, const uint32_t* b) {
    asm volatile("mma.sync.aligned.m16n8k16.row.col.f32.bf16.bf16.f32 "
        "{%0,%1,%2,%3}, {%4,%5,%6,%7}, {%8,%9}, {%0,%1,%2,%3};"
        : "+f"(d[0]), "+f"(d[1]), "+f"(d[2]), "+f"(d[3])
        : "r"(a[0]), "r"(a[1]), "r"(a[2]), "r"(a[3]), "r"(b[0]), "r"(b[1]));
}
__device__ __forceinline__ void cpasync16(uint32_t dst, const void* src, int srcbytes) {
    asm volatile("cp.async.cg.shared.global [%0], [%1], 16, %2;"
        :: "r"(dst), "l"(src), "r"(srcbytes) : "memory");
}
#define CP_COMMIT() asm volatile("cp.async.commit_group;" ::: "memory")
#define CP_WAIT1()  asm volatile("cp.async.wait_group 1;" ::: "memory")
#define CP_WAIT0()  asm volatile("cp.async.wait_group 0;" ::: "memory")

__device__ __forceinline__ void splitpack(const float* f, uint4& hi, uint4& lo) {
    uint32_t h[8], l[8];
    #pragma unroll
    for (int e = 0; e < 8; e++) {
        __nv_bfloat16 bh = __float2bfloat16(f[e]);
        float r = f[e] - __bfloat162float(bh);
        __nv_bfloat16 bl = __float2bfloat16(r);
        h[e] = (uint32_t)__bfloat16_as_ushort(bh);
        l[e] = (uint32_t)__bfloat16_as_ushort(bl);
    }
    hi = make_uint4(h[0]|(h[1]<<16), h[2]|(h[3]<<16), h[4]|(h[5]<<16), h[6]|(h[7]<<16));
    lo = make_uint4(l[0]|(l[1]<<16), l[2]|(l[3]<<16), l[4]|(l[5]<<16), l[6]|(l[7]<<16));
}

// bf16 planes: rows of 40 bf16 = 80 B (odd multiple of 16B -> conflict-free ldmatrix)
#define KC    32
#define ROWB  80
#define PLANE (128 * ROWB)             // 10240
#define OFF_AH 0
#define OFF_AL (OFF_AH + PLANE)
#define OFF_BH (OFF_AL + PLANE)
#define OFF_BL (OFF_BH + PLANE)
#define STG_A  (OFF_BL + PLANE)        // 40960; 2 x 16384 fp32 staging for A
#define STG_B  (STG_A + 32768)         // 73728; 2 x 16384 fp32 staging for B
#define G3_SMEM (STG_B + 32768)        // 106496 B

// ============ unified split-bf16 HMMA GEMM, cp.async pipelined ============
__global__ void __launch_bounds__(256, 2)
gemm3(const float* __restrict__ A, int lda, size_t sA, int aShift,
      const float* __restrict__ Bg, int ldb, size_t sB,
      float* __restrict__ Cg, int ldc, size_t sC, size_t mStrC,
      int K, int Nlimit, int dmode)
{
    extern __shared__ char smem[];
    const int n0 = blockIdx.x * 128;
    const int my = blockIdx.y;
    const int zb = blockIdx.z;
    A  += ((size_t)(zb >> aShift)) * sA + (size_t)my * 128 * lda;
    Bg += (size_t)zb * sB;
    Cg += (size_t)zb * sC + (size_t)my * mStrC;

    const uint32_t sb = smem_u32(smem);
    const int t = threadIdx.x, wid = t >> 5, lane = t & 31;
    const int wm4 = wid & 3, wn2 = wid >> 2;   // 4(m) x 2(n) warps

    const uint32_t aBase = sb + OFF_AH
        + (uint32_t)(wm4*32 + (lane & 15)) * ROWB + (uint32_t)((lane >> 4) * 16);
    const uint32_t bBase = sb + OFF_BH
        + (uint32_t)(wn2*64 + (lane & 7) + (((lane >> 4) & 1) << 3)) * ROWB
        + (uint32_t)(((lane >> 3) & 1) * 16);

    float acc[2][8][4];
    #pragma unroll
    for (int i = 0; i < 2; i++)
        #pragma unroll
        for (int j = 0; j < 8; j++)
            #pragma unroll
            for (int e = 0; e < 4; e++) acc[i][j][e] = 0.f;

    const int nc = (K + KC - 1) / KC;

    auto issue = [&](int c) {
        const int buf = c & 1;
        const int k0 = c * KC;
        const uint32_t dstA = sb + STG_A + (uint32_t)buf * 16384u;
        #pragma unroll
        for (int q = 0; q < 2; q++) {
            int idx = q * 256 + t;          // 512 items: m(128) x kg(4, 8 floats)
            int m = idx >> 2, kg = idx & 3;
            int k = k0 + kg * 8;
            const float* src = A + (size_t)m * lda + k;
            int b0 = K - k;     b0 = b0 < 0 ? 0 : (b0 > 4 ? 4 : b0); b0 *= 4;
            int b1 = K - k - 4; b1 = b1 < 0 ? 0 : (b1 > 4 ? 4 : b1); b1 *= 4;
            cpasync16(dstA + (uint32_t)idx * 32u,       b0 ? src     : A, b0);
            cpasync16(dstA + (uint32_t)idx * 32u + 16u, b1 ? src + 4 : A, b1);
        }
        const uint32_t dstB = sb + STG_B + (uint32_t)buf * 16384u;
        #pragma unroll
        for (int q = 0; q < 4; q++) {
            int idx = q * 256 + t;          // 1024 items: ke(32) x n4(32 groups of 4)
            int kel = idx >> 5, n4 = (idx & 31) * 4;
            int ke = k0 + kel;
            int Nc = n0 + n4;
            int bb = (ke < K && Nc < Nlimit) ? 16 : 0;
            const float* src;
            if (dmode) src = Bg + (size_t)(Nc >> 2) * ldb + (size_t)ke * 4;
            else       src = Bg + (size_t)ke * ldb + Nc;
            cpasync16(dstB + (uint32_t)(kel * 128 + n4) * 4u, bb ? src : Bg, bb);
        }
        CP_COMMIT();
    };

    issue(0);

    for (int c = 0; c < nc; c++) {
        const int buf = c & 1;
        if (c + 1 < nc) { issue(c + 1); CP_WAIT1(); }
        else            { CP_WAIT0(); }
        __syncthreads();

        #pragma unroll
        for (int q = 0; q < 2; q++) {
            int idx = q * 256 + t;
            int m = idx >> 2, kg = idx & 3;
            const float4* sp = (const float4*)(smem + STG_A + buf * 16384 + idx * 32);
            float4 v0 = sp[0], v1 = sp[1];
            float f[8] = {v0.x, v0.y, v0.z, v0.w, v1.x, v1.y, v1.z, v1.w};
            uint4 hi, lo;
            splitpack(f, hi, lo);
            *(uint4*)(smem + OFF_AH + m * ROWB + kg * 16) = hi;
            *(uint4*)(smem + OFF_AL + m * ROWB + kg * 16) = lo;
        }
        {
            const float* sp = (const float*)(smem + STG_B + buf * 16384);
            #pragma unroll
            for (int q = 0; q < 2; q++) {
                int idx = q * 256 + t;
                int n = idx & 127, kg = idx >> 7;
                float f[8];
                #pragma unroll
                for (int e = 0; e < 8; e++) f[e] = sp[(kg * 8 + e) * 128 + n];
                uint4 hi, lo;
                splitpack(f, hi, lo);
                *(uint4*)(smem + OFF_BH + n * ROWB + kg * 16) = hi;
                *(uint4*)(smem + OFF_BL + n * ROWB + kg * 16) = lo;
            }
        }
        __syncthreads();

        #pragma unroll
        for (int ks = 0; ks < 2; ks++) {
            const uint32_t ko = (uint32_t)ks * 32;
            uint32_t Ah[2][4], Al[2][4];
            ldmx4(Ah[0], aBase + ko);
            ldmx4(Ah[1], aBase + 1280 + ko);
            ldmx4(Al[0], aBase + PLANE + ko);
            ldmx4(Al[1], aBase + PLANE + 1280 + ko);
            uint32_t Bh[4][4], Bl[4][4];
            #pragma unroll
            for (int nq = 0; nq < 4; nq++) {
                ldmx4(Bh[nq], bBase + (uint32_t)nq * 1280 + ko);
                ldmx4(Bl[nq], bBase + (uint32_t)PLANE + (uint32_t)nq * 1280 + ko);
            }
            #pragma unroll
            for (int mi = 0; mi < 2; mi++) {
                #pragma unroll
                for (int nq = 0; nq < 4; nq++) {
                    mma16816(acc[mi][2*nq+0], Ah[mi], &Bh[nq][0]);
                    mma16816(acc[mi][2*nq+0], Ah[mi], &Bl[nq][0]);
                    mma16816(acc[mi][2*nq+0], Al[mi], &Bh[nq][0]);
                    mma16816(acc[mi][2*nq+1], Ah[mi], &Bh[nq][2]);
                    mma16816(acc[mi][2*nq+1], Ah[mi], &Bl[nq][2]);
                    mma16816(acc[mi][2*nq+1], Al[mi], &Bh[nq][2]);
                }
            }
        }
    }

    const int row0 = wm4 * 32 + (lane >> 2);
    const int col0 = wn2 * 64 + (lane & 3) * 2;
    #pragma unroll
    for (int mi = 0; mi < 2; mi++) {
        int r0 = row0 + mi * 16;
        #pragma unroll
        for (int na = 0; na < 8; na++) {
            int n = n0 + col0 + na * 8;
            float* d = acc[mi][na];
            if (!dmode) {
                if (n < Nlimit) {
                    *(float2*)(Cg + (size_t)r0 * ldc + n)       = make_float2(d[0], d[1]);
                    *(float2*)(Cg + (size_t)(r0 + 8) * ldc + n) = make_float2(d[2], d[3]);
                }
            } else {
                int c0 = ((n & 3) << 7) + (n >> 2);
                int c1 = (((n + 1) & 3) << 7) + ((n + 1) >> 2);
                Cg[(size_t)r0 * ldc + c0]       = d[0];
                Cg[(size_t)r0 * ldc + c1]       = d[1];
                Cg[(size_t)(r0 + 8) * ldc + c0] = d[2];
                Cg[(size_t)(r0 + 8) * ldc + c1] = d[3];
            }
        }
    }
}

// ---------------- MLP GEMMs (SIMT, tiny) ----------------
__device__ __forceinline__ void mlp_body(
    const float* __restrict__ A, const float* __restrict__ Bm,
    const float* __restrict__ bias, float* __restrict__ Cm, int K, int ldc)
{
    __shared__ float As[16][64];
    __shared__ float Bs[16][64];
    const int m0 = blockIdx.y * 64, n0 = blockIdx.x * 64;
    const int t  = threadIdx.x;
    const int ty = t / 16, tx = t % 16;
    float acc[4][4] = {};
    for (int k0 = 0; k0 < K; k0 += 16) {
        int r = t / 4, c = (t % 4) * 4;
        float4 va = *(const float4*)(A  + (size_t)(m0 + r) * K + k0 + c);
        As[c+0][r] = va.x; As[c+1][r] = va.y; As[c+2][r] = va.z; As[c+3][r] = va.w;
        float4 vb = *(const float4*)(Bm + (size_t)(n0 + r) * K + k0 + c);
        Bs[c+0][r] = vb.x; Bs[c+1][r] = vb.y; Bs[c+2][r] = vb.z; Bs[c+3][r] = vb.w;
        __syncthreads();
        #pragma unroll
        for (int kk = 0; kk < 16; kk++) {
            float a[4], b[4];
            #pragma unroll
            for (int q = 0; q < 4; q++) { a[q] = As[kk][ty*4+q]; b[q] = Bs[kk][tx*4+q]; }
            #pragma unroll
            for (int i2 = 0; i2 < 4; i2++)
                #pragma unroll
                for (int j2 = 0; j2 < 4; j2++) acc[i2][j2] += a[i2] * b[j2];
        }
        __syncthreads();
    }
    #pragma unroll
    for (int i2 = 0; i2 < 4; i2++)
        #pragma unroll
        for (int j2 = 0; j2 < 4; j2++) {
            int m = m0 + ty*4 + i2, n = n0 + tx*4 + j2;
            float v = acc[i2][j2] + bias[n];
            Cm[(size_t)m * ldc + n] = v > 0.f ? v : 0.f;
        }
}

__global__ void __launch_bounds__(256)
mlp_l1(const float* __restrict__ Ain,
       const float* __restrict__ W0, const float* __restrict__ b0,
       const float* __restrict__ W1, const float* __restrict__ b1,
       const float* __restrict__ W2, const float* __restrict__ b2,
       float* __restrict__ Cout)
{
    const float* W = (blockIdx.z == 0) ? W0 : (blockIdx.z == 1) ? W1 : W2;
    const float* b = (blockIdx.z == 0) ? b0 : (blockIdx.z == 1) ? b1 : b2;
    mlp_body(Ain, W, b, Cout + (size_t)blockIdx.z * MBZ * Dd, H, Dd);
}

// head (z=0, tmp slab 0) and mid (z=1, tmp slab 2), both ldc=IA
__global__ void __launch_bounds__(256)
mlp_l2hm(const float* __restrict__ tmp,
         const float* __restrict__ Wh2, const float* __restrict__ bh2,
         const float* __restrict__ Wm2, const float* __restrict__ bm2,
         float* __restrict__ head, float* __restrict__ mid)
{
    if (blockIdx.z == 0) mlp_body(tmp,               Wh2, bh2, head, Dd, IA);
    else                 mlp_body(tmp + 2*MBZ*Dd,    Wm2, bm2, mid,  Dd, IA);
}

__global__ void __launch_bounds__(256)
mlp_l2t(const float* __restrict__ tmp,
        const float* __restrict__ Wt2, const float* __restrict__ bt2,
        float* __restrict__ tail)
{
    mlp_body(tmp + MBZ*Dd, Wt2, bt2, tail, Dd, Dd);
}

// ---------------- prep: mem^T split-bf16 planes + set_ones ----------------
// grid (12, 2), 256 threads: transpose memory[b][z][hb*64..+64] -> memh/meml [b][h][z]
__global__ void __launch_bounds__(256)
prep(const float* __restrict__ mem, __nv_bfloat16* __restrict__ mh,
     __nv_bfloat16* __restrict__ ml, float* __restrict__ head, float* __restrict__ mid)
{
    __shared__ float tile[128][68];
    const int hb = blockIdx.x, b = blockIdx.y;
    const int t = threadIdx.x;
    const float* src = mem + (size_t)b * S * H + hb * 64;
    #pragma unroll
    for (int q = 0; q < 8; q++) {
        int idx = q * 256 + t;            // 2048 float4: z(128) x hq(16)
        int z = idx >> 4, hq = (idx & 15) * 4;
        float4 v = *(const float4*)(src + (size_t)z * H + hq);
        tile[z][hq] = v.x; tile[z][hq+1] = v.y; tile[z][hq+2] = v.z; tile[z][hq+3] = v.w;
    }
    __syncthreads();
    #pragma unroll
    for (int q = 0; q < 16; q++) {
        int idx = q * 256 + t;            // 4096: h(64) x zp(64 pairs)
        int h = idx >> 6, zp = idx & 63;
        float a0 = tile[zp*2][h], a1 = tile[zp*2+1][h];
        __nv_bfloat16 h0 = __float2bfloat16(a0);
        __nv_bfloat16 h1 = __float2bfloat16(a1);
        __nv_bfloat16 l0 = __float2bfloat16(a0 - __bfloat162float(h0));
        __nv_bfloat16 l1 = __float2bfloat16(a1 - __bfloat162float(h1));
        size_t off = ((size_t)b * H + hb * 64 + h) * S + zp * 2;
        *(uint32_t*)(mh + off) = (uint32_t)__bfloat16_as_ushort(h0) | ((uint32_t)__bfloat16_as_ushort(h1) << 16);
        *(uint32_t*)(ml + off) = (uint32_t)__bfloat16_as_ushort(l0) | ((uint32_t)__bfloat16_as_ushort(l1) << 16);
    }
    if (hb == 0 && b == 0) {
        head[(size_t)t * IA + Dd] = 1.f; head[(size_t)t * IA + Dd + 1] = 0.f;
        head[(size_t)t * IA + Dd + 2] = 0.f; head[(size_t)t * IA + Dd + 3] = 0.f;
        mid [(size_t)t * IA + Dd] = 1.f; mid [(size_t)t * IA + Dd + 1] = 0.f;
        mid [(size_t)t * IA + Dd + 2] = 0.f; mid [(size_t)t * IA + Dd + 3] = 0.f;
    }
}

// ---------------- Stage E: masked softmax + HMMA relu(alpha^T mem).Vw + Vb ----
// grid (yq=4, x=128, b=2), 256 threads. 128 rows m=(yl,r) per CTA.
// unnormalized e stored split-bf16; 1/sum folded into final scale (relu homogeneous).
#define E_AROW 272                       // 128 k * 2B + 16 pad (odd 16B multiple)
#define E_APH 0
#define E_APL (E_APH + 128*E_AROW)       // 34816
#define E_MTH (E_APL + 128*E_AROW)       // 69632
#define E_MTL (E_MTH + 64*E_AROW)       // 87040  (mem tile rows: 64 h x 272B)
#define E_VWS (E_MTL + 64*E_AROW)       // 104448
#define E_OUT (E_VWS + 1024)            // 105472
#define E_SINV (E_OUT + 512)            // 105984
#define E_SMEM (E_SINV + 512)           // 106496

__global__ void __launch_bounds__(256, 2)
stageE2(const float* __restrict__ score,
        const __nv_bfloat16* __restrict__ memh, const __nv_bfloat16* __restrict__ meml,
        const float* __restrict__ Vw, const float* __restrict__ Vb,
        float* __restrict__ out)
{
    extern __shared__ char smem[];
    const uint32_t sb = smem_u32(smem);
    float* outs = (float*)(smem + E_OUT);
    float* sinv = (float*)(smem + E_SINV);
    float* vws  = (float*)(smem + E_VWS);
    const int yq = blockIdx.x, x = blockIdx.y, b = blockIdx.z;
    const int t = threadIdx.x, wid = t >> 5, lane = t & 31;

    // ---- phase 1: masked softmax (unnormalized), split-bf16 into A planes ----
    {
        const int m = t >> 1, half = t & 1;      // row m, z-half
        const int y = yq * 32 + (m >> 2), r = m & 3;
        const float* srow = score + ((((size_t)(b*S + x))*S + y)*4 + r) * S + half * 64;
        float v[64];
        float mx = -1e30f;
        #pragma unroll 4
        for (int zq = 0; zq < 16; zq++) {
            float4 w = *(const float4*)(srow + zq*4);
            float ww[4] = {w.x, w.y, w.z, w.w};
            #pragma unroll
            for (int e = 0; e < 4; e++) {
                int z = half*64 + zq*4 + e;
                float val = (z >= x && z <= y) ? ww[e] : -1000000.0f;
                v[zq*4+e] = val;
                mx = fmaxf(mx, val);
            }
        }
        mx = fmaxf(mx, __shfl_xor_sync(0xffffffffu, mx, 1));
        float ssum = 0.f;
        #pragma unroll
        for (int z = 0; z < 64; z++) { float e = __expf(v[z] - mx); v[z] = e; ssum += e; }
        ssum += __shfl_xor_sync(0xffffffffu, ssum, 1);
        if (half == 0) sinv[m] = 1.f / ssum;
        // store unnormalized e split-bf16 (pairs)
        char* rowh = smem + E_APH + m * E_AROW + half * 128;
        char* rowl = smem + E_APL + m * E_AROW + half * 128;
        #pragma unroll
        for (int zp = 0; zp < 32; zp++) {
            float a0 = v[zp*2], a1 = v[zp*2+1];
            __nv_bfloat16 h0 = __float2bfloat16(a0);
            __nv_bfloat16 h1 = __float2bfloat16(a1);
            __nv_bfloat16 l0 = __float2bfloat16(a0 - __bfloat162float(h0));
            __nv_bfloat16 l1 = __float2bfloat16(a1 - __bfloat162float(h1));
            *(uint32_t*)(rowh + zp*4) = (uint32_t)__bfloat16_as_ushort(h0) | ((uint32_t)__bfloat16_as_ushort(h1) << 16);
            *(uint32_t*)(rowl + zp*4) = (uint32_t)__bfloat16_as_ushort(l0) | ((uint32_t)__bfloat16_as_ushort(l1) << 16);
        }
        if (t < 128) outs[t] = 0.f;
    }

    // ---- phase 2: TSu = e^T mem via 3-term HMMA; relu, dot Vw per h-block ----
    const int wm4 = wid & 3, wn2 = wid >> 2;    // 4(m) x 2(n), warp tile 32x32
    const uint32_t aBase = sb + E_APH
        + (uint32_t)(wm4*32 + (lane & 15)) * E_AROW + (uint32_t)((lane >> 4) * 16);
    const uint32_t bBase = sb + E_MTH
        + (uint32_t)(wn2*32 + (lane & 7) + (((lane >> 4) & 1) << 3)) * E_AROW
        + (uint32_t)(((lane >> 3) & 1) * 16);
    const int rIdx = (lane >> 2) & 3;
    float part[4] = {0.f, 0.f, 0.f, 0.f};       // rows: mi*16 + half8*8 offsets

    for (int hb = 0; hb < 12; hb++) {
        __syncthreads();                        // planes ready / prev mma done
        const int h0 = hb * 64;
        // load mem^T tiles [h][z] (64 rows x 256B) via cp.async
        // each 16B chunk = 8 z values; 16 chunks cover z=0..127
        #pragma unroll
        for (int q = 0; q < 4; q++) {
            int idx = q * 256 + t;              // 1024: h(64) x chunk(16)
            int hr = idx >> 4, z8 = (idx & 15) * 8;
            size_t goff = ((size_t)b * H + h0 + hr) * S + z8;
            cpasync16(sb + E_MTH + (uint32_t)hr * E_AROW + (uint32_t)z8 * 2, memh + goff, 16);
            cpasync16(sb + E_MTL + (uint32_t)hr * E_AROW + (uint32_t)z8 * 2, meml + goff, 16);
        }
        CP_COMMIT();
        { int r = t >> 6, hl = t & 63; vws[r*64 + hl] = Vw[(size_t)r * H + h0 + hl]; }
        CP_WAIT0();
        __syncthreads();

        float acc[2][4][4];
        #pragma unroll
        for (int i = 0; i < 2; i++)
            #pragma unroll
            for (int j = 0; j < 4; j++)
                #pragma unroll
                for (int e = 0; e < 4; e++) acc[i][j][e] = 0.f;

        #pragma unroll
        for (int ks = 0; ks < 8; ks++) {
            const uint32_t ko = (uint32_t)ks * 32;
            uint32_t Ah[2][4], Al[2][4];
            ldmx4(Ah[0], aBase + ko);
            ldmx4(Ah[1], aBase + 16u*E_AROW + ko);
            ldmx4(Al[0], aBase + (uint32_t)(E_APL - E_APH) + ko);
            ldmx4(Al[1], aBase + (uint32_t)(E_APL - E_APH) + 16u*E_AROW + ko);
            uint32_t Bh[2][4], Bl[2][4];
            #pragma unroll
            for (int nq = 0; nq < 2; nq++) {
                ldmx4(Bh[nq], bBase + (uint32_t)nq * 16u*E_AROW + ko);
                ldmx4(Bl[nq], bBase + (uint32_t)(E_MTL - E_MTH) + (uint32_t)nq * 16u*E_AROW + ko);
            }
            #pragma unroll
            for (int mi = 0; mi < 2; mi++) {
                #pragma unroll
                for (int nq = 0; nq < 2; nq++) {
                    mma16816(acc[mi][2*nq+0], Ah[mi], &Bh[nq][0]);
                    mma16816(acc[mi][2*nq+0], Ah[mi], &Bl[nq][0]);
                    mma16816(acc[mi][2*nq+0], Al[mi], &Bh[nq][0]);
                    mma16816(acc[mi][2*nq+1], Ah[mi], &Bh[nq][2]);
                    mma16816(acc[mi][2*nq+1], Ah[mi], &Bl[nq][2]);
                    mma16816(acc[mi][2*nq+1], Al[mi], &Bh[nq][2]);
                }
            }
        }
        // consume: relu + dot Vw
        #pragma unroll
        for (int mi = 0; mi < 2; mi++)
            #pragma unroll
            for (int na = 0; na < 4; na++) {
                int hl = wn2*32 + na*8 + (lane & 3)*2;
                #pragma unroll
                for (int e = 0; e < 4; e++) {
                    float vv = acc[mi][na][e];
                    vv = vv > 0.f ? vv : 0.f;
                    part[mi*2 + (e >> 1)] += vv * vws[rIdx*64 + hl + (e & 1)];
                }
            }
    }

    // ---- reduce partials ----
    {
        int rbase = wm4*32 + (lane >> 2);
        atomicAdd(&outs[rbase],      part[0]);
        atomicAdd(&outs[rbase + 8],  part[1]);
        atomicAdd(&outs[rbase + 16], part[2]);
        atomicAdd(&outs[rbase + 24], part[3]);
    }
    __syncthreads();
    if (t < 128) {
        int y = yq*32 + (t >> 2), r = t & 3;
        out[(((size_t)(b*S + x))*S + y)*4 + r] = outs[t] * sinv[t] + Vb[r];
    }
}

// ---------------------------------------------------------------------------
extern "C" void kernel_launch(void* const* d_in, const int* in_sizes, int n_in,
                              void* d_out, int out_size)
{
    const float* memory = (const float*)d_in[0];
    const float* Wh1 = (const float*)d_in[1];  const float* bh1 = (const float*)d_in[2];
    const float* Wh2 = (const float*)d_in[3];  const float* bh2 = (const float*)d_in[4];
    const float* Wt1 = (const float*)d_in[5];  const float* bt1 = (const float*)d_in[6];
    const float* Wt2 = (const float*)d_in[7];  const float* bt2 = (const float*)d_in[8];
    const float* Wm1 = (const float*)d_in[9];  const float* bm1 = (const float*)d_in[10];
    const float* Wm2 = (const float*)d_in[11]; const float* bm2 = (const float*)d_in[12];
    const float* Wtri = (const float*)d_in[13];
    const float* Vw  = (const float*)d_in[14]; const float* Vb  = (const float*)d_in[15];
    float* out = (float*)d_out;

    float *tmp, *head, *mid, *tail, *t1, *u, *score;
    __nv_bfloat16 *mh, *ml;
    cudaGetSymbolAddress((void**)&tmp,   g_tmp);
    cudaGetSymbolAddress((void**)&head,  g_head);
    cudaGetSymbolAddress((void**)&mid,   g_mid);
    cudaGetSymbolAddress((void**)&tail,  g_tail);
    cudaGetSymbolAddress((void**)&t1,    g_t1);
    cudaGetSymbolAddress((void**)&u,     g_u);
    cudaGetSymbolAddress((void**)&score, g_sc);
    cudaGetSymbolAddress((void**)&mh,    g_memh);
    cudaGetSymbolAddress((void**)&ml,    g_meml);

    dim3 gm(Dd/64, MBZ/64);
    // 4 launches before stageB -> with harness's 1 pre-launch, ncu -s5 profiles stageB
    prep<<<dim3(12, 2), 256>>>(memory, mh, ml, head, mid);                 // 1
    mlp_l1<<<dim3(Dd/64, MBZ/64, 3), 256>>>(memory, Wh1, bh1, Wt1, bt1,
                                            Wm1, bm1, tmp);                // 2
    mlp_l2hm<<<dim3(Dd/64, MBZ/64, 2), 256>>>(tmp, Wh2, bh2, Wm2, bm2,
                                              head, mid);                  // 3
    mlp_l2t<<<gm, 256>>>(tmp, Wt2, bt2, tail);                             // 4

    cudaFuncSetAttribute(gemm3, cudaFuncAttributeMaxDynamicSharedMemorySize, G3_SMEM);

    // Stage B (launch 5): t1[b,i,z,(jr)] = sum_k tail[b*128+z,k] * W[i,k,(jr)]
    gemm3<<<dim3(13, 2, I), 256, G3_SMEM>>>(
        tail, Dd, 0, 0,
        Wtri, NJR, (size_t)Dd * NJR,
        t1, NJR, (size_t)128 * NJR, (size_t)I * 128 * NJR,
        Dd, NJR, 0);

    // Stage C: u[b,x,(zjr)] = sum_i head[b*128+x,i] * t1[b,i,(zjr)]
    gemm3<<<dim3(NBIG/128, 1, 2), 256, G3_SMEM>>>(
        head, IA, (size_t)128 * IA, 0,
        t1, NBIG, (size_t)I * NBIG,
        u, NBIG, (size_t)128 * NBIG, 0,
        I, NBIG, 0);

    // Stage D: score[b,x,y,r,z] = sum_j mid[b*128+y,j] * u[b,x,z,j,r]
    gemm3<<<dim3(4, 1, 256), 256, G3_SMEM>>>(
        mid, IA, (size_t)128 * IA, 7,
        u, NJR, (size_t)NBIG,
        score, 512, (size_t)65536, 0,
        I, 512, 1);

    cudaFuncSetAttribute(stageE2, cudaFuncAttributeMaxDynamicSharedMemorySize, E_SMEM);
    stageE2<<<dim3(4, 128, 2), 256, E_SMEM>>>(score, mh, ml, Vw, Vb, out);
}